// round 12
// baseline (speedup 1.0000x reference)
#include <cuda_runtime.h>

// Problem constants: B=8, T=4096, C=32 (embedding), D=64 (head)
#define B_  8
#define T_  4096
#define C_  32
#define D_  64
#define NQT128 32            // 128-wide query tiles per batch
#define NCHUNK 8             // k-chunks per query tile (each <=8 k-passes of 64)

typedef unsigned long long ull;

// ---- attn kernel smem layout (floats), single-buffered x tiles ----
#define QP2    132                     // ys row stride (128 q + pad)
#define YS_OFF 0                       // ys[32][132]  = 4224
#define XT_OFF 4224                    // xT[32][68]   = 2176
#define XN_OFF 6400                    // xN[64][36]   = 2304
#define PS_OFF 8704                    // Ps[128][68]  = 8704
#define SM_FLOATS 17408                // 69632 B  -> 3 CTAs/SM

// M = Wq * Wk^T  (32x32)
__device__ float g_M[C_ * C_];
// split-K partials: slot = ((b*32+qt)*8 + chunk)
__device__ float g_partZ[B_ * NQT128 * NCHUNK * 128 * 32];   // 33.5 MB
__device__ float g_partL[B_ * NQT128 * NCHUNK * 128];

// ---------------------------------------------------------------------------
// packed f32x2 helpers (sm_103a FFMA2 path)
// ---------------------------------------------------------------------------
__device__ __forceinline__ ull pack2(float a, float b) {
    ull r; asm("mov.b64 %0, {%1, %2};" : "=l"(r) : "f"(a), "f"(b)); return r;
}
__device__ __forceinline__ float2 unpack2(ull v) {
    float2 r; asm("mov.b64 {%0, %1}, %2;" : "=f"(r.x), "=f"(r.y) : "l"(v)); return r;
}
__device__ __forceinline__ void fma2(ull& d, ull a, ull b) {
    asm("fma.rn.f32x2 %0, %1, %2, %0;" : "+l"(d) : "l"(a), "l"(b));
}

// ---------------------------------------------------------------------------
// Kernel 0: M = Wq * Wk^T via conflict-free smem (1 CTA, 256 threads, ~6us).
// ---------------------------------------------------------------------------
__global__ __launch_bounds__(256) void m_kernel(
    const float* __restrict__ Wk, const float* __restrict__ Wq)
{
    __shared__ float Wqt[64 * 33];
    __shared__ float Wkt[64 * 33];

    const int tid = threadIdx.x;
    const float4* wq = (const float4*)Wq;
    const float4* wk = (const float4*)Wk;
    #pragma unroll
    for (int it = 0; it < 2; it++) {
        int lin = tid + it * 256;            // 0..511: 32 rows x 16 float4
        int r = lin >> 4, d0 = (lin & 15) * 4;
        float4 q4 = wq[lin];
        Wqt[(d0 + 0) * 33 + r] = q4.x;
        Wqt[(d0 + 1) * 33 + r] = q4.y;
        Wqt[(d0 + 2) * 33 + r] = q4.z;
        Wqt[(d0 + 3) * 33 + r] = q4.w;
        float4 k4 = wk[lin];
        Wkt[(d0 + 0) * 33 + r] = k4.x;
        Wkt[(d0 + 1) * 33 + r] = k4.y;
        Wkt[(d0 + 2) * 33 + r] = k4.z;
        Wkt[(d0 + 3) * 33 + r] = k4.w;
    }
    __syncthreads();

    const int i  = tid >> 3;           // 0..31
    const int j0 = (tid & 7) * 4;      // 0,4,..,28
    float a0 = 0.f, a1 = 0.f, a2 = 0.f, a3 = 0.f;
    #pragma unroll 16
    for (int d = 0; d < D_; d++) {
        float qv = Wqt[d * 33 + i];
        const float* wkr = &Wkt[d * 33 + j0];
        a0 += qv * wkr[0];
        a1 += qv * wkr[1];
        a2 += qv * wkr[2];
        a3 += qv * wkr[3];
    }
    g_M[i * C_ + j0 + 0] = a0;
    g_M[i * C_ + j0 + 1] = a1;
    g_M[i * C_ + j0 + 2] = a2;
    g_M[i * C_ + j0 + 3] = a3;
}

// ---------------------------------------------------------------------------
// Kernel 1: split-K attention partials.  3 CTAs/SM (single-buffered x tiles,
// register prefetch hides the LDG latency).
// One CTA = (b, qt, chunk): k-tiles [8*chunk, min(2qt+2, 8*chunk+8)).
//   y = x_q*M;  S = y x_k^T;  p = exp(S);  Zpart += p x_k;  lpart += rowsum(p)
// ---------------------------------------------------------------------------
__global__ __launch_bounds__(256, 3) void attn_kernel(const float* __restrict__ x)
{
    const int b     = blockIdx.y;
    const int qt    = (NQT128 - 1) - (blockIdx.x >> 3);  // heaviest first
    const int chunk = blockIdx.x & 7;
    const int k0    = chunk * 8;
    const int k1e   = 2 * qt + 2;                        // one past last k-tile
    if (k0 >= k1e) return;                               // empty chunk
    const int k1    = (k1e < k0 + 8) ? k1e : (k0 + 8);

    extern __shared__ float smf[];
    float* ys = smf + YS_OFF;
    float* xT = smf + XT_OFF;
    float* xN = smf + XN_OFF;
    float* Ps = smf + PS_OFF;

    const int tid = threadIdx.x;
    const int tx  = tid & 15, ty = tid >> 4;   // S-pass: 8q x 4k per thread
    const int zr  = tid >> 3;                  // Z-pass rows zr + 32*i
    const int zc  = (tid & 7) * 4;             // Z-pass cols zc..zc+3

    const float* xb = x + b * T_ * C_;

    // ---- stage x_q (128x32) into Ps ----
    {
        const float4* xq = (const float4*)(xb + qt * 128 * C_);
        #pragma unroll
        for (int it = 0; it < 4; it++) {
            int lin = tid + it * 256;
            int r = lin >> 3, c4 = lin & 7;
            *(float4*)&Ps[r * 68 + c4 * 4] = xq[lin];
        }
    }
    __syncthreads();

    // ---- y = x_q * M -> ys (transposed [c'][q]) ----
    {
        const int c0 = tx * 2;
        float a0[8], a1[8];
        #pragma unroll
        for (int i = 0; i < 8; i++) { a0[i] = 0.f; a1[i] = 0.f; }
        #pragma unroll 8
        for (int c = 0; c < C_; c++) {
            float2 m2 = *(const float2*)&g_M[c * C_ + c0];
            #pragma unroll
            for (int i = 0; i < 8; i++) {
                float xv = Ps[(ty * 8 + i) * 68 + c];
                a0[i] += xv * m2.x;
                a1[i] += xv * m2.y;
            }
        }
        #pragma unroll
        for (int i = 0; i < 8; i++) {
            ys[(c0 + 0) * QP2 + ty * 8 + i] = a0[i];
            ys[(c0 + 1) * QP2 + ty * 8 + i] = a1[i];
        }
    }

    // ---- preload k-tile k0 (natural + transposed) ----
    {
        const float4* xg = (const float4*)(xb + k0 * 64 * C_);
        float4 p0 = xg[tid], p1 = xg[tid + 256];
        int r = tid >> 3, c4 = tid & 7;
        *(float4*)&xN[r * 36 + c4 * 4] = p0;
        xT[(c4 * 4 + 0) * 68 + r] = p0.x;
        xT[(c4 * 4 + 1) * 68 + r] = p0.y;
        xT[(c4 * 4 + 2) * 68 + r] = p0.z;
        xT[(c4 * 4 + 3) * 68 + r] = p0.w;
        int r2 = r + 32;
        *(float4*)&xN[r2 * 36 + c4 * 4] = p1;
        xT[(c4 * 4 + 0) * 68 + r2] = p1.x;
        xT[(c4 * 4 + 1) * 68 + r2] = p1.y;
        xT[(c4 * 4 + 2) * 68 + r2] = p1.z;
        xT[(c4 * 4 + 3) * 68 + r2] = p1.w;
    }

    float l_i[8];
    #pragma unroll
    for (int i = 0; i < 8; i++) l_i[i] = 0.f;
    ull z2[4][2];
    #pragma unroll
    for (int i = 0; i < 4; i++) { z2[i][0] = 0ull; z2[i][1] = 0ull; }

    for (int kt = k0; kt < k1; kt++) {
        __syncthreads();   // (A) x tile + ys stores visible; Ps free for reuse

        // prefetch next k-tile into registers (stored after the Z-pass)
        float4 p0, p1;
        const bool pf = (kt + 1 < k1);
        if (pf) {
            const float4* xg = (const float4*)(xb + (kt + 1) * 64 * C_);
            p0 = xg[tid]; p1 = xg[tid + 256];
        }

        // ---- S = y * x_k^T : 8q x 4k, q-paired FFMA2, pair-free q loads ----
        ull s2[4][4];   // [k-col j][q-pair i2]
        #pragma unroll
        for (int j = 0; j < 4; j++)
            #pragma unroll
            for (int i2 = 0; i2 < 4; i2++) s2[j][i2] = 0ull;

        #pragma unroll 8
        for (int c = 0; c < C_; c++) {
            ulonglong2 qa = *(const ulonglong2*)&ys[c * QP2 + ty * 8];
            ulonglong2 qb = *(const ulonglong2*)&ys[c * QP2 + ty * 8 + 4];
            float4 kv = *(const float4*)&xT[c * 68 + tx * 4];
            ull kd[4] = { pack2(kv.x, kv.x), pack2(kv.y, kv.y),
                          pack2(kv.z, kv.z), pack2(kv.w, kv.w) };
            #pragma unroll
            for (int j = 0; j < 4; j++) {
                fma2(s2[j][0], qa.x, kd[j]);
                fma2(s2[j][1], qa.y, kd[j]);
                fma2(s2[j][2], qb.x, kd[j]);
                fma2(s2[j][3], qb.y, kd[j]);
            }
        }

        // ---- unpack -> mask -> exp -> Ps, one q-pair at a time ----
        const bool diag = (kt >= 2 * qt);
        const int  koff = (kt - 2 * qt) * 64;
        #pragma unroll
        for (int i2 = 0; i2 < 4; i2++) {
            float e[2][4];
            #pragma unroll
            for (int j = 0; j < 4; j++) {
                float2 u = unpack2(s2[j][i2]);
                e[0][j] = u.x;
                e[1][j] = u.y;
            }
            #pragma unroll
            for (int r = 0; r < 2; r++) {
                const int i = 2 * i2 + r;
                if (diag) {
                    #pragma unroll
                    for (int j = 0; j < 4; j++)
                        if (koff + tx * 4 + j > ty * 8 + i) e[r][j] = -1e30f;
                }
                float e0 = __expf(e[r][0]);
                float e1 = __expf(e[r][1]);
                float e2 = __expf(e[r][2]);
                float e3 = __expf(e[r][3]);
                l_i[i] += (e0 + e1) + (e2 + e3);
                *(float4*)&Ps[(ty * 8 + i) * 68 + tx * 4] =
                    make_float4(e0, e1, e2, e3);
            }
        }
        __syncthreads();   // (B) Ps visible; S-pass done reading xT

        // ---- Z += P * x_k : rows zr+32i, cols zc..zc+3, c-paired FFMA2 ----
        #pragma unroll 4
        for (int k4 = 0; k4 < 16; k4++) {
            ulonglong2 xp[4];
            float4 pr[4];
            #pragma unroll
            for (int kk = 0; kk < 4; kk++)
                xp[kk] = *(const ulonglong2*)&xN[(k4 * 4 + kk) * 36 + zc];
            #pragma unroll
            for (int i = 0; i < 4; i++)
                pr[i] = *(const float4*)&Ps[(zr + 32 * i) * 68 + k4 * 4];

            #pragma unroll
            for (int i = 0; i < 4; i++) {
                const float* pv = (const float*)&pr[i];
                #pragma unroll
                for (int kk = 0; kk < 4; kk++) {
                    ull pd = pack2(pv[kk], pv[kk]);
                    fma2(z2[i][0], pd, xp[kk].x);
                    fma2(z2[i][1], pd, xp[kk].y);
                }
            }
        }
        __syncthreads();   // (C) Z-pass done reading xN/Ps

        // ---- store prefetched tile into the (single) buffer ----
        if (pf) {
            int r = tid >> 3, c4 = tid & 7;
            *(float4*)&xN[r * 36 + c4 * 4] = p0;
            xT[(c4 * 4 + 0) * 68 + r] = p0.x;
            xT[(c4 * 4 + 1) * 68 + r] = p0.y;
            xT[(c4 * 4 + 2) * 68 + r] = p0.z;
            xT[(c4 * 4 + 3) * 68 + r] = p0.w;
            int r2 = r + 32;
            *(float4*)&xN[r2 * 36 + c4 * 4] = p1;
            xT[(c4 * 4 + 0) * 68 + r2] = p1.x;
            xT[(c4 * 4 + 1) * 68 + r2] = p1.y;
            xT[(c4 * 4 + 2) * 68 + r2] = p1.z;
            xT[(c4 * 4 + 3) * 68 + r2] = p1.w;
        }
    }

    // ---- write partials ----
    const int islot = (b * NQT128 + qt) * NCHUNK + chunk;

    #pragma unroll
    for (int i = 0; i < 8; i++) {   // partial row sums (reduced over tx)
        float rs = l_i[i];
        rs += __shfl_xor_sync(0xffffffffu, rs, 8);
        rs += __shfl_xor_sync(0xffffffffu, rs, 4);
        rs += __shfl_xor_sync(0xffffffffu, rs, 2);
        rs += __shfl_xor_sync(0xffffffffu, rs, 1);
        if (tx == 0) g_partL[islot * 128 + ty * 8 + i] = rs;
    }

    float* zp = g_partZ + islot * (128 * 32);
    #pragma unroll
    for (int i = 0; i < 4; i++) {
        float2 a = unpack2(z2[i][0]);
        float2 c = unpack2(z2[i][1]);
        *(float4*)&zp[(zr + 32 * i) * 32 + zc] = make_float4(a.x, a.y, c.x, c.y);
    }
}

// ---------------------------------------------------------------------------
// Kernel 2: reduce partials, out = (Z / l) * Wv.
// One CTA = (b, qt, half): 64 q-rows.  512 CTAs.
// ---------------------------------------------------------------------------
__global__ __launch_bounds__(256) void reduce_kernel(
    const float* __restrict__ Wv, float* __restrict__ out)
{
    __shared__ float Zs[64][36];
    __shared__ float Wvs[32][68];
    __shared__ float lv[64];

    const int qt   = blockIdx.x >> 1;
    const int half = blockIdx.x & 1;
    const int b    = blockIdx.y;
    const int tid  = threadIdx.x;
    const int nc   = (2 * qt + 1) / 8 + 1;   // valid chunks for this qt
    const int base = (b * NQT128 + qt) * NCHUNK;
    const int row0 = half * 64;

    float4 acc[2];
    #pragma unroll
    for (int it = 0; it < 2; it++) acc[it] = make_float4(0.f, 0.f, 0.f, 0.f);
    for (int s = 0; s < nc; s++) {
        const float4* zp = (const float4*)(g_partZ + (base + s) * (128 * 32) + row0 * 32);
        #pragma unroll
        for (int it = 0; it < 2; it++) {
            float4 v = zp[tid + it * 256];
            acc[it].x += v.x; acc[it].y += v.y; acc[it].z += v.z; acc[it].w += v.w;
        }
    }
    if (tid < 64) {
        float ls = 0.f;
        for (int s = 0; s < nc; s++)
            ls += g_partL[(base + s) * 128 + row0 + tid];
        lv[tid] = 1.f / ls;
    }
    __syncthreads();

    #pragma unroll
    for (int it = 0; it < 2; it++) {
        int lin = tid + it * 256;
        int r = lin >> 3, c4 = lin & 7;
        float li = lv[r];
        *(float4*)&Zs[r][c4 * 4] = make_float4(acc[it].x * li, acc[it].y * li,
                                               acc[it].z * li, acc[it].w * li);
    }
    {
        const float4* wg = (const float4*)Wv;
        #pragma unroll
        for (int it = 0; it < 2; it++) {
            int lin = tid + it * 256;
            int r = lin >> 4, c4 = lin & 15;
            *(float4*)&Wvs[r][c4 * 4] = wg[lin];
        }
    }
    __syncthreads();

    const int tx = tid & 15, ty = tid >> 4;
    float o[4][4];
    #pragma unroll
    for (int i = 0; i < 4; i++)
        #pragma unroll
        for (int j = 0; j < 4; j++) o[i][j] = 0.f;

    #pragma unroll 4
    for (int c = 0; c < C_; c++) {
        float4 w4 = *(const float4*)&Wvs[c][tx * 4];
        #pragma unroll
        for (int i = 0; i < 4; i++) {
            float zv = Zs[ty + 16 * i][c];
            o[i][0] += zv * w4.x; o[i][1] += zv * w4.y;
            o[i][2] += zv * w4.z; o[i][3] += zv * w4.w;
        }
    }

    float* Og = out + (b * T_ + qt * 128 + row0) * D_;
    #pragma unroll
    for (int i = 0; i < 4; i++)
        *(float4*)&Og[(ty + 16 * i) * D_ + tx * 4] =
            make_float4(o[i][0], o[i][1], o[i][2], o[i][3]);
}

// ---------------------------------------------------------------------------
extern "C" void kernel_launch(void* const* d_in, const int* in_sizes, int n_in,
                              void* d_out, int out_size)
{
    const float* x  = (const float*)d_in[0];
    const float* Wk = (const float*)d_in[1];
    const float* Wq = (const float*)d_in[2];
    const float* Wv = (const float*)d_in[3];
    float* out = (float*)d_out;

    m_kernel<<<1, 256>>>(Wk, Wq);

    const int smem = SM_FLOATS * (int)sizeof(float);   // 69632 B
    cudaFuncSetAttribute(attn_kernel, cudaFuncAttributeMaxDynamicSharedMemorySize, smem);
    attn_kernel<<<dim3(NQT128 * NCHUNK, B_), 256, smem>>>(x);

    reduce_kernel<<<dim3(NQT128 * 2, B_), 256>>>(Wv, out);
}